// round 15
// baseline (speedup 1.0000x reference)
#include <cuda_runtime.h>
#include <cuda_fp16.h>
#include <math.h>
#include <stdint.h>

// ---------------- problem constants ----------------
#define BB    4
#define SS    2048
#define DD    1024
#define NN    256
#define NCOMB 288           // 256 (WB) + 32 (Wg)
#define DFF   2730
#define DFFP  2752
#define ROWS  (BB*SS)
#define EPSV  1e-6f

// ---------------- scratch ----------------
__device__ __align__(16) __half g_xsh[(size_t)ROWS * DD];
__device__ __align__(16) float  g_gates[(size_t)ROWS * 32];
__device__ __align__(16) float  g_bx [(size_t)ROWS * NN];
__device__ __align__(16) __half g_hsh[(size_t)ROWS * NN];
__device__ __align__(16) __half g_s1h[(size_t)ROWS * DFFP];   // pad cols stay 0 (BSS)
__device__ __align__(16) __half g_wcb[NCOMB * DD];            // WB rows 0-255, Wg rows 256-287
__device__ __align__(16) __half g_wch[DD * NN];
__device__ __align__(16) __half g_w1h[(size_t)DFF * DD];
__device__ __align__(16) __half g_w2h[(size_t)DFF * DD];
__device__ __align__(16) __half g_w3h[(size_t)DD * DFFP];
__device__ __align__(16) float  g_LQ[16 * 16 * 16];
__device__ __align__(16) float  g_RQ[16 * 16 * 16];

// ---------------- helpers ----------------
__device__ __forceinline__ float sigf(float v) { return 1.f / (1.f + expf(-v)); }
__device__ __forceinline__ uint32_t smem_u32(const void* p) {
    uint32_t a;
    asm("{ .reg .u64 t; cvta.to.shared.u64 t, %1; cvt.u32.u64 %0, t; }" : "=r"(a) : "l"(p));
    return a;
}
__device__ __forceinline__ void mma_f16(float* d, const uint32_t* a, const uint32_t* b) {
    asm volatile("mma.sync.aligned.m16n8k16.row.col.f32.f16.f16.f32 "
        "{%0,%1,%2,%3}, {%4,%5,%6,%7}, {%8,%9}, {%0,%1,%2,%3};"
        : "+f"(d[0]), "+f"(d[1]), "+f"(d[2]), "+f"(d[3])
        : "r"(a[0]), "r"(a[1]), "r"(a[2]), "r"(a[3]), "r"(b[0]), "r"(b[1]));
}
__device__ __forceinline__ void ldsm4(uint32_t* r, uint32_t addr) {
    asm volatile("ldmatrix.sync.aligned.m8n8.x4.shared.b16 {%0,%1,%2,%3}, [%4];"
        : "=r"(r[0]), "=r"(r[1]), "=r"(r[2]), "=r"(r[3]) : "r"(addr));
}
__device__ __forceinline__ void cpa16(uint32_t dst, const void* src, int sz) {
    asm volatile("cp.async.ca.shared.global [%0], [%1], 16, %2;"
                 :: "r"(dst), "l"(src), "r"(sz) : "memory");
}
#define CP_COMMIT() asm volatile("cp.async.commit_group;" ::: "memory")

// ---------------- cayley ----------------
__global__ void cayley_kernel(const float* __restrict__ Lskew,
                              const float* __restrict__ Rskew) {
    int t = threadIdx.x;
    if (t >= 32) return;
    const float* Sk = (t < 16) ? (Lskew + t * 256) : (Rskew + (t - 16) * 256);
    float*       Q  = (t < 16) ? (g_LQ + t * 256)  : (g_RQ + (t - 16) * 256);
    float M[16][16], X[16][16];
    for (int i = 0; i < 16; i++)
        for (int j = 0; j < 16; j++) {
            float a = Sk[i * 16 + j] - Sk[j * 16 + i];
            float d = (i == j) ? 1.f : 0.f;
            M[i][j] = d + a; X[i][j] = d - a;
        }
    for (int p = 0; p < 16; p++) {
        float piv = 1.f / M[p][p];
        for (int j = 0; j < 16; j++) { M[p][j] *= piv; X[p][j] *= piv; }
        for (int r = 0; r < 16; r++) {
            if (r == p) continue;
            float f = M[r][p];
            for (int j = 0; j < 16; j++) { M[r][j] -= f * M[p][j]; X[r][j] -= f * X[p][j]; }
        }
    }
    for (int i = 0; i < 16; i++)
        for (int j = 0; j < 16; j++) Q[i * 16 + j] = X[i][j];
}

// ---------------- small prep: wcb (WB+Wg) and wch ----------------
#define P0 (NN*DD)
#define P1 (32*DD)
#define P2 (DD*NN)
#define P3 (DFF*DD)
#define PSMALL ((size_t)P0 + P1 + P2)
__global__ void prep_small_kernel(const float* __restrict__ Wg, const float* __restrict__ WB,
                                  const float* __restrict__ WC) {
    size_t i = ((size_t)blockIdx.x * 256 + threadIdx.x) * 2;
    if (i >= PSMALL) return;
    const float* src; __half* dst; size_t off = i;
    if      (off < P0)         { src = WB; dst = g_wcb; }
    else if ((off -= P0) < P1) { src = Wg; dst = g_wcb + P0; }
    else    { off -= P1;         src = WC; dst = g_wch; }
    float2 v = *reinterpret_cast<const float2*>(src + off);
    *reinterpret_cast<__half2*>(dst + off) = __floats2half2_rn(v.x, v.y);
}

// ---------------- rmsnorm (fp32 in, fp16 out) ----------------
__global__ void rmsnorm_h_kernel(const float* __restrict__ x,
                                 const float* __restrict__ w,
                                 __half* __restrict__ out) {
    int row = blockIdx.x;
    int tid = threadIdx.x;
    const float4* xr = reinterpret_cast<const float4*>(x + (size_t)row * DD);
    const float4* wr = reinterpret_cast<const float4*>(w);
    float4 v = xr[tid];
    float ss = v.x * v.x + v.y * v.y + v.z * v.z + v.w * v.w;
    for (int o = 16; o > 0; o >>= 1) ss += __shfl_down_sync(0xffffffffu, ss, o);
    __shared__ float red[8];
    __shared__ float tot;
    if ((tid & 31) == 0) red[tid >> 5] = ss;
    __syncthreads();
    if (tid == 0) {
        float s = 0.f;
        for (int k = 0; k < 8; k++) s += red[k];
        tot = rsqrtf(s * (1.f / DD) + EPSV);
    }
    __syncthreads();
    float inv = tot;
    float4 wv = wr[tid];
    __half2* o2 = reinterpret_cast<__half2*>(out + (size_t)row * DD + tid * 4);
    o2[0] = __floats2half2_rn(v.x * wv.x * inv, v.y * wv.y * inv);
    o2[1] = __floats2half2_rn(v.z * wv.z * inv, v.w * wv.w * inv);
}

// ================= fp16 mma.sync GEMM (NSTAGE=4, occ 2) =================
#define EPI_BIASRES 2
#define EPI_RES     3
#define EPI_BXG     6

#define STG_PITCH 80
#define STG_A     10240
#define STG_SZ    20480
#define NSTAGE    4

template <int EPI>
__global__ __launch_bounds__(256, 2)
void mma_h_kernel(const __half* __restrict__ A, int lda,
                  const __half* __restrict__ B, int ldb, int nvalid,
                  float* __restrict__ C, int ldc,
                  const float* __restrict__ bias,
                  const float* __restrict__ auxf,
                  int K)
{
    extern __shared__ __align__(16) char smch[];
    const uint32_t sb = smem_u32(smch);
    const int t = threadIdx.x, ln = t & 31, w = t >> 5;
    const int wm = w >> 2, wn = w & 3;
    const int bm = blockIdx.y * 128, bn = blockIdx.x * 128;

    uint32_t adst[2], bdst[2];
    const __half* gA[2];
    const __half* gB[2];
    int bsz[2];
#pragma unroll
    for (int p = 0; p < 2; p++) {
        int c = t + p * 256;
        int m = c >> 2, cb = (c & 3) * 16, koff = (c & 3) * 8;
        adst[p] = (uint32_t)(m * STG_PITCH + cb);
        bdst[p] = (uint32_t)(STG_A + m * STG_PITCH + cb);
        gA[p] = A + (size_t)(bm + m) * lda + koff;
        int gn = bn + m;
        bool val = (gn < nvalid);
        gB[p] = B + (size_t)(val ? gn : 0) * ldb + koff;
        bsz[p] = val ? 16 : 0;
    }
    const int q = ln >> 3, lr = ln & 7;
    const uint32_t aBase = sb + (uint32_t)((wm * 64 + (q & 1) * 8 + lr) * STG_PITCH + (q >> 1) * 16);
    const uint32_t bBase = sb + (uint32_t)(STG_A + (wn * 32 + (q >> 1) * 8 + lr) * STG_PITCH + (q & 1) * 16);

    const int nCh = K >> 5;
    auto issue = [&](int i) {
        if (i < nCh) {
            uint32_t base = sb + (uint32_t)(i % NSTAGE) * STG_SZ;
#pragma unroll
            for (int p = 0; p < 2; p++) {
                cpa16(base + adst[p], gA[p] + i * 32, 16);
                cpa16(base + bdst[p], gB[p] + i * 32, bsz[p]);
            }
        }
        CP_COMMIT();
    };

    float acc[4][4][4];
#pragma unroll
    for (int i = 0; i < 4; i++)
#pragma unroll
        for (int j = 0; j < 4; j++)
#pragma unroll
            for (int r = 0; r < 4; r++) acc[i][j][r] = 0.f;

    issue(0); issue(1); issue(2);
    for (int i = 0; i < nCh; i++) {
        asm volatile("cp.async.wait_group %0;" :: "n"(NSTAGE - 2) : "memory");
        __syncthreads();
        issue(i + NSTAGE - 1);
        uint32_t so = (uint32_t)(i % NSTAGE) * STG_SZ;
#pragma unroll
        for (int ks = 0; ks < 2; ks++) {
            uint32_t af[4][4], bf[4][2];
#pragma unroll
            for (int mf = 0; mf < 4; mf++)
                ldsm4(af[mf], aBase + so + mf * (16 * STG_PITCH) + ks * 32);
#pragma unroll
            for (int nfp = 0; nfp < 2; nfp++) {
                uint32_t rr[4];
                ldsm4(rr, bBase + so + nfp * (16 * STG_PITCH) + ks * 32);
                bf[nfp * 2 + 0][0] = rr[0]; bf[nfp * 2 + 0][1] = rr[1];
                bf[nfp * 2 + 1][0] = rr[2]; bf[nfp * 2 + 1][1] = rr[3];
            }
#pragma unroll
            for (int ii = 0; ii < 4; ii++)
#pragma unroll
                for (int j = 0; j < 4; j++)
                    mma_f16(acc[ii][j], af[ii], bf[j]);
        }
    }

    const int g4 = ln >> 2, t4 = ln & 3;
#pragma unroll
    for (int ii = 0; ii < 4; ii++) {
        int row0 = bm + wm * 64 + ii * 16 + g4;
#pragma unroll
        for (int j = 0; j < 4; j++) {
            int col = bn + wn * 32 + j * 8 + t4 * 2;
            if (col < nvalid) {
#pragma unroll
                for (int h = 0; h < 2; h++) {
                    int r = row0 + h * 8;
                    float v0 = acc[ii][j][h * 2 + 0];
                    float v1 = acc[ii][j][h * 2 + 1];
                    if (EPI == EPI_BXG) {
                        if (col < NN) {
                            v0 += bias[col]; v1 += bias[col + 1];
                            size_t idx = (size_t)r * NN + col;
                            *reinterpret_cast<float2*>(C + idx) = make_float2(v0, v1);
                        } else {
                            int gc = col - NN;
                            v0 = sigf(v0 + auxf[gc]); v1 = sigf(v1 + auxf[gc + 1]);
                            size_t gidx = (size_t)r * 32 + gc;
                            *reinterpret_cast<float2*>(g_gates + gidx) = make_float2(v0, v1);
                        }
                    } else {
                        size_t idx = (size_t)r * ldc + col;
                        if (EPI == EPI_BIASRES) { v0 += bias[col] + auxf[idx]; v1 += bias[col + 1] + auxf[idx + 1]; }
                        if (EPI == EPI_RES)     { v0 += auxf[idx]; v1 += auxf[idx + 1]; }
                        *reinterpret_cast<float2*>(C + idx) = make_float2(v0, v1);
                    }
                }
            }
        }
    }
}

// ---------------- fused FF: BN=128 dual acc, 256t, occ 1, 5-stage ----------------
#define FF_STG_SZ (STG_A * 3)
#define FF_NSTAGE 5

__global__ __launch_bounds__(256, 1)
void ff_fused_kernel(const __half* __restrict__ A, int lda,
                     const __half* __restrict__ B1, const __half* __restrict__ B2,
                     int ldb, int nvalid,
                     __half* __restrict__ C, int ldc, int K)
{
    extern __shared__ __align__(16) char smch[];
    const uint32_t sb = smem_u32(smch);
    const int t = threadIdx.x, ln = t & 31, w = t >> 5;
    const int wm = w >> 2, wn = w & 3;
    const int bm = blockIdx.y * 128, bn = blockIdx.x * 128;

    uint32_t adst[2], bdst[2];
    const __half* gA[2];
    const __half* gB1[2];
    const __half* gB2[2];
    int bsz[2];
#pragma unroll
    for (int p = 0; p < 2; p++) {
        int c = t + p * 256;
        int m = c >> 2, cb = (c & 3) * 16, koff = (c & 3) * 8;
        adst[p] = (uint32_t)(m * STG_PITCH + cb);
        bdst[p] = (uint32_t)(STG_A + m * STG_PITCH + cb);
        gA[p] = A + (size_t)(bm + m) * lda + koff;
        int gn = bn + m;
        bool val = (gn < nvalid);
        gB1[p] = B1 + (size_t)(val ? gn : 0) * ldb + koff;
        gB2[p] = B2 + (size_t)(val ? gn : 0) * ldb + koff;
        bsz[p] = val ? 16 : 0;
    }
    const int q = ln >> 3, lr = ln & 7;
    const uint32_t aBase = sb + (uint32_t)((wm * 64 + (q & 1) * 8 + lr) * STG_PITCH + (q >> 1) * 16);
    const uint32_t bBase = sb + (uint32_t)(STG_A + (wn * 32 + (q >> 1) * 8 + lr) * STG_PITCH + (q & 1) * 16);

    const int nCh = K >> 5;
    auto issue = [&](int i) {
        if (i < nCh) {
            uint32_t base = sb + (uint32_t)(i % FF_NSTAGE) * FF_STG_SZ;
#pragma unroll
            for (int p = 0; p < 2; p++) {
                cpa16(base + adst[p],          gA[p]  + i * 32, 16);
                cpa16(base + bdst[p],          gB1[p] + i * 32, bsz[p]);
                cpa16(base + bdst[p] + STG_A,  gB2[p] + i * 32, bsz[p]);
            }
        }
        CP_COMMIT();
    };

    float ac1[4][4][4], ac2[4][4][4];
#pragma unroll
    for (int i = 0; i < 4; i++)
#pragma unroll
        for (int j = 0; j < 4; j++)
#pragma unroll
            for (int r = 0; r < 4; r++) { ac1[i][j][r] = 0.f; ac2[i][j][r] = 0.f; }

    issue(0); issue(1); issue(2); issue(3);
    for (int i = 0; i < nCh; i++) {
        asm volatile("cp.async.wait_group %0;" :: "n"(FF_NSTAGE - 2) : "memory");
        __syncthreads();
        issue(i + FF_NSTAGE - 1);
        uint32_t so = (uint32_t)(i % FF_NSTAGE) * FF_STG_SZ;
#pragma unroll
        for (int ks = 0; ks < 2; ks++) {
            uint32_t af[4][4], b1[4][2], b2[4][2];
#pragma unroll
            for (int mf = 0; mf < 4; mf++)
                ldsm4(af[mf], aBase + so + mf * (16 * STG_PITCH) + ks * 32);
#pragma unroll
            for (int nfp = 0; nfp < 2; nfp++) {
                uint32_t rr[4];
                ldsm4(rr, bBase + so + nfp * (16 * STG_PITCH) + ks * 32);
                b1[nfp * 2 + 0][0] = rr[0]; b1[nfp * 2 + 0][1] = rr[1];
                b1[nfp * 2 + 1][0] = rr[2]; b1[nfp * 2 + 1][1] = rr[3];
                ldsm4(rr, bBase + so + STG_A + nfp * (16 * STG_PITCH) + ks * 32);
                b2[nfp * 2 + 0][0] = rr[0]; b2[nfp * 2 + 0][1] = rr[1];
                b2[nfp * 2 + 1][0] = rr[2]; b2[nfp * 2 + 1][1] = rr[3];
            }
#pragma unroll
            for (int ii = 0; ii < 4; ii++)
#pragma unroll
                for (int j = 0; j < 4; j++) {
                    mma_f16(ac1[ii][j], af[ii], b1[j]);
                    mma_f16(ac2[ii][j], af[ii], b2[j]);
                }
        }
    }

    const int g4 = ln >> 2, t4 = ln & 3;
#pragma unroll
    for (int ii = 0; ii < 4; ii++) {
        int row0 = bm + wm * 64 + ii * 16 + g4;
#pragma unroll
        for (int j = 0; j < 4; j++) {
            int col = bn + wn * 32 + j * 8 + t4 * 2;
            if (col < nvalid) {
#pragma unroll
                for (int h = 0; h < 2; h++) {
                    int r = row0 + h * 8;
                    size_t idx = (size_t)r * ldc + col;
                    float a0 = ac1[ii][j][h * 2 + 0], a1 = ac1[ii][j][h * 2 + 1];
                    float b0 = ac2[ii][j][h * 2 + 0], b1v = ac2[ii][j][h * 2 + 1];
                    float v0 = a0 * sigf(a0) * b0;
                    float v1 = a1 * sigf(a1) * b1v;
                    *reinterpret_cast<__half2*>(C + idx) = __floats2half2_rn(v0, v1);
                }
            }
        }
    }
}

// ---------------- fused scan + big weight prep ----------------
// CHK=64: 32 chunks x 4 batches = 128 scan CTAs, 224 serial steps each.
#define CHK   64
#define WNUP  160
#define SCAN_BLOCKS 128
#define PREP_BLOCKS 448

__global__ void scanprep_kernel(const float* __restrict__ gates,
                                const float* __restrict__ Bx,
                                __half* __restrict__ hs,
                                const float* __restrict__ w1,
                                const float* __restrict__ w2,
                                const float* __restrict__ w3) {
    __shared__ float hp[2][16 * 17];
    if (blockIdx.x >= SCAN_BLOCKS) {
        size_t pb = blockIdx.x - SCAN_BLOCKS;
        size_t stride = (size_t)(gridDim.x - SCAN_BLOCKS) * 256;
        size_t tid0 = pb * 256 + threadIdx.x;
        for (size_t i = tid0; i < (size_t)P3; i += stride) {
            size_t off = i * 2;
            const float* src; __half* dst;
            if (off < (size_t)P3) { src = w1; dst = g_w1h; }
            else { off -= (size_t)P3; src = w2; dst = g_w2h; }
            float2 v = *reinterpret_cast<const float2*>(src + off);
            *reinterpret_cast<__half2*>(dst + off) = __floats2half2_rn(v.x, v.y);
        }
        size_t pairs3 = (size_t)DD * DFFP / 2;
        for (size_t i = tid0; i < pairs3; i += stride) {
            size_t j2 = i * 2;
            int d = (int)(j2 / DFFP);
            int j = (int)(j2 % DFFP);
            __half2 o;
            if (j < DFF) {
                float2 v = *reinterpret_cast<const float2*>(w3 + (size_t)d * DFF + j);
                o = __floats2half2_rn(v.x, v.y);
            } else {
                o = __floats2half2_rn(0.f, 0.f);
            }
            *reinterpret_cast<__half2*>(g_w3h + (size_t)d * DFFP + j) = o;
        }
        return;
    }
    int chunk = blockIdx.x & 31, bat = blockIdx.x >> 5;
    int s0 = chunk * CHK, send = s0 + CHK;
    int sw = (chunk == 0) ? 0 : s0 - WNUP;
    if (sw < 0) sw = 0;
    int t = threadIdx.x;
    int c = t >> 4, i = t & 15;

    float Rrow[16], Lrow[16];
#pragma unroll
    for (int j = 0; j < 16; j++) {
        Rrow[j] = g_RQ[(c * 16 + i) * 16 + j];
        Lrow[j] = g_LQ[(i * 16 + c) * 16 + j];
    }
    float val = 0.f;

    size_t base = (size_t)bat * SS;
    float bx_n = Bx[(base + sw) * NN + t];
    float al_n = gates[(base + sw) * 32 + i];
    float be_n = gates[(base + sw) * 32 + 16 + c];

    for (int s = sw; s < send; s++) {
        float bx = bx_n, al = al_n, be = be_n;
        if (s + 1 < send) {
            size_t rn = base + s + 1;
            bx_n = Bx[rn * NN + t];
            al_n = gates[rn * 32 + i];
            be_n = gates[rn * 32 + 16 + c];
        }
        float acc0 = 0.f, acc1 = 0.f;
#pragma unroll
        for (int j = 0; j < 16; j += 2) {
            float h0 = __shfl_sync(0xffffffffu, val, j, 16);
            float h1 = __shfl_sync(0xffffffffu, val, j + 1, 16);
            acc0 = fmaf(Rrow[j], h0, acc0);
            acc1 = fmaf(Rrow[j + 1], h1, acc1);
        }
        float* hpb = hp[s & 1];
        hpb[i * 17 + c] = be * (acc0 + acc1);
        __syncthreads();
        float acc2 = 0.f, acc3 = 0.f;
#pragma unroll
        for (int j = 0; j < 16; j += 2) {
            acc2 = fmaf(Lrow[j],     hpb[i * 17 + j],     acc2);
            acc3 = fmaf(Lrow[j + 1], hpb[i * 17 + j + 1], acc3);
        }
        val = al * (acc2 + acc3) + bx;
        if (s >= s0) hs[(base + s) * NN + t] = __float2half(val);
    }
}

// ---------------- launcher ----------------
#define GEMM_SMEM (NSTAGE * STG_SZ)
#define FF_SMEM   (FF_NSTAGE * FF_STG_SZ)

extern "C" void kernel_launch(void* const* d_in, const int* in_sizes, int n_in,
                              void* d_out, int out_size) {
    const float* x     = (const float*)d_in[0];
    const float* Lskew = (const float*)d_in[1];
    const float* Rskew = (const float*)d_in[2];
    const float* Wg    = (const float*)d_in[3];
    const float* bg    = (const float*)d_in[4];
    const float* WB    = (const float*)d_in[5];
    const float* bB    = (const float*)d_in[6];
    const float* WC    = (const float*)d_in[7];
    const float* bC    = (const float*)d_in[8];
    const float* n1w   = (const float*)d_in[9];
    const float* n2w   = (const float*)d_in[10];
    const float* w1    = (const float*)d_in[11];
    const float* w2    = (const float*)d_in[12];
    const float* w3    = (const float*)d_in[13];
    float* out = (float*)d_out;

    __half *xsh, *hsh, *s1h, *wcb, *wch, *w1h, *w2h, *w3h;
    float *gatesb, *bxb;
    cudaGetSymbolAddress((void**)&xsh,    g_xsh);
    cudaGetSymbolAddress((void**)&gatesb, g_gates);
    cudaGetSymbolAddress((void**)&bxb,    g_bx);
    cudaGetSymbolAddress((void**)&hsh,    g_hsh);
    cudaGetSymbolAddress((void**)&s1h,    g_s1h);
    cudaGetSymbolAddress((void**)&wcb,    g_wcb);
    cudaGetSymbolAddress((void**)&wch,    g_wch);
    cudaGetSymbolAddress((void**)&w1h,    g_w1h);
    cudaGetSymbolAddress((void**)&w2h,    g_w2h);
    cudaGetSymbolAddress((void**)&w3h,    g_w3h);

    cudaFuncSetAttribute(mma_h_kernel<EPI_BXG>,     cudaFuncAttributeMaxDynamicSharedMemorySize, GEMM_SMEM);
    cudaFuncSetAttribute(mma_h_kernel<EPI_BIASRES>, cudaFuncAttributeMaxDynamicSharedMemorySize, GEMM_SMEM);
    cudaFuncSetAttribute(mma_h_kernel<EPI_RES>,     cudaFuncAttributeMaxDynamicSharedMemorySize, GEMM_SMEM);
    cudaFuncSetAttribute(ff_fused_kernel,           cudaFuncAttributeMaxDynamicSharedMemorySize, FF_SMEM);

    // 1. Cayley
    cayley_kernel<<<1, 32>>>(Lskew, Rskew);
    // 2. small prep (wcb, wch)
    prep_small_kernel<<<(int)((PSMALL / 2 + 255) / 256), 256>>>(Wg, WB, WC);
    // 3. xs = half(rmsnorm(x, norm1_w))
    rmsnorm_h_kernel<<<ROWS, 256>>>(x, n1w, xsh);
    // 4. combined: Bx = xs@WB^T + bB, gates = sigmoid(xs@Wg^T + bg)
    {
        dim3 g((NCOMB + 127) / 128, ROWS / 128);
        mma_h_kernel<EPI_BXG><<<g, 256, GEMM_SMEM>>>(xsh, DD, wcb, DD, NCOMB, bxb, NN, bB, bg, DD);
    }
    // 5. fused: windowed scan (blocks 0-127, CHK=64) + big weight prep (blocks 128+)
    scanprep_kernel<<<SCAN_BLOCKS + PREP_BLOCKS, 256>>>(gatesb, bxb, hsh, w1, w2, w3);
    // 6. out = x + hs @ WC^T + bC   (BM=128 — R13 proven)
    {
        dim3 g(DD / 128, ROWS / 128);
        mma_h_kernel<EPI_BIASRES><<<g, 256, GEMM_SMEM>>>(hsh, NN, wch, NN, DD, out, DD, bC, x, NN);
    }
    // 7. xs = half(rmsnorm(out, norm2_w))
    rmsnorm_h_kernel<<<ROWS, 256>>>(out, n2w, xsh);
    // 8. s1h = half(silu(xs@w1^T) * (xs@w2^T))   (fused FF, 5-stage)
    {
        dim3 g((DFF + 127) / 128, ROWS / 128);
        ff_fused_kernel<<<g, 256, FF_SMEM>>>(xsh, DD, w1h, w2h, DD, DFF, s1h, DFFP, DD);
    }
    // 9. out += s1h @ w3h^T   (BM=128 — R13 proven)
    {
        dim3 g(DD / 128, ROWS / 128);
        mma_h_kernel<EPI_RES><<<g, 256, GEMM_SMEM>>>(s1h, DFFP, w3h, DFFP, DD, out, DD, nullptr, out, DFFP);
    }
}

// round 16
// speedup vs baseline: 1.0824x; 1.0824x over previous
#include <cuda_runtime.h>
#include <cuda_fp16.h>
#include <math.h>
#include <stdint.h>

// ---------------- problem constants ----------------
#define BB    4
#define SS    2048
#define DD    1024
#define NN    256
#define NCOMB 288           // 256 (WB) + 32 (Wg)
#define DFF   2730
#define DFFP  2752
#define ROWS  (BB*SS)
#define EPSV  1e-6f

// ---------------- scratch ----------------
__device__ __align__(16) __half g_xsh[(size_t)ROWS * DD];
__device__ __align__(16) float  g_gates[(size_t)ROWS * 32];
__device__ __align__(16) float  g_bx [(size_t)ROWS * NN];
__device__ __align__(16) __half g_hsh[(size_t)ROWS * NN];
__device__ __align__(16) __half g_s1h[(size_t)ROWS * DFFP];   // pad cols stay 0 (BSS)
__device__ __align__(16) __half g_wcb[NCOMB * DD];            // WB rows 0-255, Wg rows 256-287
__device__ __align__(16) __half g_wch[DD * NN];
__device__ __align__(16) __half g_w1h[(size_t)DFF * DD];
__device__ __align__(16) __half g_w2h[(size_t)DFF * DD];
__device__ __align__(16) __half g_w3h[(size_t)DD * DFFP];
__device__ __align__(16) float  g_LQ[16 * 16 * 16];
__device__ __align__(16) float  g_RQ[16 * 16 * 16];

// ---------------- helpers ----------------
__device__ __forceinline__ float sigf(float v) { return 1.f / (1.f + expf(-v)); }
__device__ __forceinline__ uint32_t smem_u32(const void* p) {
    uint32_t a;
    asm("{ .reg .u64 t; cvta.to.shared.u64 t, %1; cvt.u32.u64 %0, t; }" : "=r"(a) : "l"(p));
    return a;
}
__device__ __forceinline__ void mma_f16(float* d, const uint32_t* a, const uint32_t* b) {
    asm volatile("mma.sync.aligned.m16n8k16.row.col.f32.f16.f16.f32 "
        "{%0,%1,%2,%3}, {%4,%5,%6,%7}, {%8,%9}, {%0,%1,%2,%3};"
        : "+f"(d[0]), "+f"(d[1]), "+f"(d[2]), "+f"(d[3])
        : "r"(a[0]), "r"(a[1]), "r"(a[2]), "r"(a[3]), "r"(b[0]), "r"(b[1]));
}
__device__ __forceinline__ void ldsm4(uint32_t* r, uint32_t addr) {
    asm volatile("ldmatrix.sync.aligned.m8n8.x4.shared.b16 {%0,%1,%2,%3}, [%4];"
        : "=r"(r[0]), "=r"(r[1]), "=r"(r[2]), "=r"(r[3]) : "r"(addr));
}
__device__ __forceinline__ void cpa16(uint32_t dst, const void* src, int sz) {
    asm volatile("cp.async.ca.shared.global [%0], [%1], 16, %2;"
                 :: "r"(dst), "l"(src), "r"(sz) : "memory");
}
#define CP_COMMIT() asm volatile("cp.async.commit_group;" ::: "memory")

// ---------------- fused init: cayley + small weight prep + rmsnorm1 ----------------
#define P0 (NN*DD)
#define P1 (32*DD)
#define P2 (DD*NN)
#define P3 (DFF*DD)
#define PSMALL ((size_t)P0 + P1 + P2)
#define PREP_SMALL_BLOCKS ((int)((PSMALL / 2 + 255) / 256))   // 1088
#define INIT_BLOCKS (1 + PREP_SMALL_BLOCKS + ROWS)

__global__ void init_kernel(const float* __restrict__ x,
                            const float* __restrict__ n1w,
                            const float* __restrict__ Lskew,
                            const float* __restrict__ Rskew,
                            const float* __restrict__ Wg,
                            const float* __restrict__ WB,
                            const float* __restrict__ WC,
                            __half* __restrict__ xout) {
    __shared__ float red[8];
    __shared__ float tot;
    if (blockIdx.x == 0) {
        // ---- cayley (threads 0-31) ----
        int t = threadIdx.x;
        if (t >= 32) return;
        const float* Sk = (t < 16) ? (Lskew + t * 256) : (Rskew + (t - 16) * 256);
        float*       Q  = (t < 16) ? (g_LQ + t * 256)  : (g_RQ + (t - 16) * 256);
        float M[16][16], X[16][16];
        for (int i = 0; i < 16; i++)
            for (int j = 0; j < 16; j++) {
                float a = Sk[i * 16 + j] - Sk[j * 16 + i];
                float d = (i == j) ? 1.f : 0.f;
                M[i][j] = d + a; X[i][j] = d - a;
            }
        for (int p = 0; p < 16; p++) {
            float piv = 1.f / M[p][p];
            for (int j = 0; j < 16; j++) { M[p][j] *= piv; X[p][j] *= piv; }
            for (int r = 0; r < 16; r++) {
                if (r == p) continue;
                float f = M[r][p];
                for (int j = 0; j < 16; j++) { M[r][j] -= f * M[p][j]; X[r][j] -= f * X[p][j]; }
            }
        }
        for (int i = 0; i < 16; i++)
            for (int j = 0; j < 16; j++) Q[i * 16 + j] = X[i][j];
        return;
    }
    if (blockIdx.x <= PREP_SMALL_BLOCKS) {
        // ---- small weight prep ----
        size_t i = ((size_t)(blockIdx.x - 1) * 256 + threadIdx.x) * 2;
        if (i >= PSMALL) return;
        const float* src; __half* dst; size_t off = i;
        if      (off < P0)         { src = WB; dst = g_wcb; }
        else if ((off -= P0) < P1) { src = Wg; dst = g_wcb + P0; }
        else    { off -= P1;         src = WC; dst = g_wch; }
        float2 v = *reinterpret_cast<const float2*>(src + off);
        *reinterpret_cast<__half2*>(dst + off) = __floats2half2_rn(v.x, v.y);
        return;
    }
    // ---- rmsnorm row ----
    int row = blockIdx.x - 1 - PREP_SMALL_BLOCKS;
    int tid = threadIdx.x;
    const float4* xr = reinterpret_cast<const float4*>(x + (size_t)row * DD);
    const float4* wr = reinterpret_cast<const float4*>(n1w);
    float4 v = xr[tid];
    float ss = v.x * v.x + v.y * v.y + v.z * v.z + v.w * v.w;
    for (int o = 16; o > 0; o >>= 1) ss += __shfl_down_sync(0xffffffffu, ss, o);
    if ((tid & 31) == 0) red[tid >> 5] = ss;
    __syncthreads();
    if (tid == 0) {
        float s = 0.f;
        for (int k = 0; k < 8; k++) s += red[k];
        tot = rsqrtf(s * (1.f / DD) + EPSV);
    }
    __syncthreads();
    float inv = tot;
    float4 wv = wr[tid];
    __half2* o2 = reinterpret_cast<__half2*>(xout + (size_t)row * DD + tid * 4);
    o2[0] = __floats2half2_rn(v.x * wv.x * inv, v.y * wv.y * inv);
    o2[1] = __floats2half2_rn(v.z * wv.z * inv, v.w * wv.w * inv);
}

// ---------------- rmsnorm (standalone, for norm2) ----------------
__global__ void rmsnorm_h_kernel(const float* __restrict__ x,
                                 const float* __restrict__ w,
                                 __half* __restrict__ out) {
    int row = blockIdx.x;
    int tid = threadIdx.x;
    const float4* xr = reinterpret_cast<const float4*>(x + (size_t)row * DD);
    const float4* wr = reinterpret_cast<const float4*>(w);
    float4 v = xr[tid];
    float ss = v.x * v.x + v.y * v.y + v.z * v.z + v.w * v.w;
    for (int o = 16; o > 0; o >>= 1) ss += __shfl_down_sync(0xffffffffu, ss, o);
    __shared__ float red[8];
    __shared__ float tot;
    if ((tid & 31) == 0) red[tid >> 5] = ss;
    __syncthreads();
    if (tid == 0) {
        float s = 0.f;
        for (int k = 0; k < 8; k++) s += red[k];
        tot = rsqrtf(s * (1.f / DD) + EPSV);
    }
    __syncthreads();
    float inv = tot;
    float4 wv = wr[tid];
    __half2* o2 = reinterpret_cast<__half2*>(out + (size_t)row * DD + tid * 4);
    o2[0] = __floats2half2_rn(v.x * wv.x * inv, v.y * wv.y * inv);
    o2[1] = __floats2half2_rn(v.z * wv.z * inv, v.w * wv.w * inv);
}

// ================= fp16 mma.sync GEMM (NSTAGE=4, occ 2) =================
#define EPI_BIASRES 2
#define EPI_RES     3
#define EPI_BXG     6

#define STG_PITCH 80
#define STG_A     10240
#define STG_SZ    20480
#define NSTAGE    4

template <int EPI>
__global__ __launch_bounds__(256, 2)
void mma_h_kernel(const __half* __restrict__ A, int lda,
                  const __half* __restrict__ B, int ldb, int nvalid,
                  float* __restrict__ C, int ldc,
                  const float* __restrict__ bias,
                  const float* __restrict__ auxf,
                  int K)
{
    extern __shared__ __align__(16) char smch[];
    const uint32_t sb = smem_u32(smch);
    const int t = threadIdx.x, ln = t & 31, w = t >> 5;
    const int wm = w >> 2, wn = w & 3;
    const int bm = blockIdx.y * 128, bn = blockIdx.x * 128;

    uint32_t adst[2], bdst[2];
    const __half* gA[2];
    const __half* gB[2];
    int bsz[2];
#pragma unroll
    for (int p = 0; p < 2; p++) {
        int c = t + p * 256;
        int m = c >> 2, cb = (c & 3) * 16, koff = (c & 3) * 8;
        adst[p] = (uint32_t)(m * STG_PITCH + cb);
        bdst[p] = (uint32_t)(STG_A + m * STG_PITCH + cb);
        gA[p] = A + (size_t)(bm + m) * lda + koff;
        int gn = bn + m;
        bool val = (gn < nvalid);
        gB[p] = B + (size_t)(val ? gn : 0) * ldb + koff;
        bsz[p] = val ? 16 : 0;
    }
    const int q = ln >> 3, lr = ln & 7;
    const uint32_t aBase = sb + (uint32_t)((wm * 64 + (q & 1) * 8 + lr) * STG_PITCH + (q >> 1) * 16);
    const uint32_t bBase = sb + (uint32_t)(STG_A + (wn * 32 + (q >> 1) * 8 + lr) * STG_PITCH + (q & 1) * 16);

    const int nCh = K >> 5;
    auto issue = [&](int i) {
        if (i < nCh) {
            uint32_t base = sb + (uint32_t)(i % NSTAGE) * STG_SZ;
#pragma unroll
            for (int p = 0; p < 2; p++) {
                cpa16(base + adst[p], gA[p] + i * 32, 16);
                cpa16(base + bdst[p], gB[p] + i * 32, bsz[p]);
            }
        }
        CP_COMMIT();
    };

    float acc[4][4][4];
#pragma unroll
    for (int i = 0; i < 4; i++)
#pragma unroll
        for (int j = 0; j < 4; j++)
#pragma unroll
            for (int r = 0; r < 4; r++) acc[i][j][r] = 0.f;

    issue(0); issue(1); issue(2);
    for (int i = 0; i < nCh; i++) {
        asm volatile("cp.async.wait_group %0;" :: "n"(NSTAGE - 2) : "memory");
        __syncthreads();
        issue(i + NSTAGE - 1);
        uint32_t so = (uint32_t)(i % NSTAGE) * STG_SZ;
#pragma unroll
        for (int ks = 0; ks < 2; ks++) {
            uint32_t af[4][4], bf[4][2];
#pragma unroll
            for (int mf = 0; mf < 4; mf++)
                ldsm4(af[mf], aBase + so + mf * (16 * STG_PITCH) + ks * 32);
#pragma unroll
            for (int nfp = 0; nfp < 2; nfp++) {
                uint32_t rr[4];
                ldsm4(rr, bBase + so + nfp * (16 * STG_PITCH) + ks * 32);
                bf[nfp * 2 + 0][0] = rr[0]; bf[nfp * 2 + 0][1] = rr[1];
                bf[nfp * 2 + 1][0] = rr[2]; bf[nfp * 2 + 1][1] = rr[3];
            }
#pragma unroll
            for (int ii = 0; ii < 4; ii++)
#pragma unroll
                for (int j = 0; j < 4; j++)
                    mma_f16(acc[ii][j], af[ii], bf[j]);
        }
    }

    const int g4 = ln >> 2, t4 = ln & 3;
#pragma unroll
    for (int ii = 0; ii < 4; ii++) {
        int row0 = bm + wm * 64 + ii * 16 + g4;
#pragma unroll
        for (int j = 0; j < 4; j++) {
            int col = bn + wn * 32 + j * 8 + t4 * 2;
            if (col < nvalid) {
#pragma unroll
                for (int h = 0; h < 2; h++) {
                    int r = row0 + h * 8;
                    float v0 = acc[ii][j][h * 2 + 0];
                    float v1 = acc[ii][j][h * 2 + 1];
                    if (EPI == EPI_BXG) {
                        if (col < NN) {
                            v0 += bias[col]; v1 += bias[col + 1];
                            size_t idx = (size_t)r * NN + col;
                            *reinterpret_cast<float2*>(C + idx) = make_float2(v0, v1);
                        } else {
                            int gc = col - NN;
                            v0 = sigf(v0 + auxf[gc]); v1 = sigf(v1 + auxf[gc + 1]);
                            size_t gidx = (size_t)r * 32 + gc;
                            *reinterpret_cast<float2*>(g_gates + gidx) = make_float2(v0, v1);
                        }
                    } else {
                        size_t idx = (size_t)r * ldc + col;
                        if (EPI == EPI_BIASRES) { v0 += bias[col] + auxf[idx]; v1 += bias[col + 1] + auxf[idx + 1]; }
                        if (EPI == EPI_RES)     { v0 += auxf[idx]; v1 += auxf[idx + 1]; }
                        *reinterpret_cast<float2*>(C + idx) = make_float2(v0, v1);
                    }
                }
            }
        }
    }
}

// ---------------- fused FF: BN=128 dual acc, 256t, occ 1, 5-stage ----------------
#define FF_STG_SZ (STG_A * 3)
#define FF_NSTAGE 5

__global__ __launch_bounds__(256, 1)
void ff_fused_kernel(const __half* __restrict__ A, int lda,
                     const __half* __restrict__ B1, const __half* __restrict__ B2,
                     int ldb, int nvalid,
                     __half* __restrict__ C, int ldc, int K)
{
    extern __shared__ __align__(16) char smch[];
    const uint32_t sb = smem_u32(smch);
    const int t = threadIdx.x, ln = t & 31, w = t >> 5;
    const int wm = w >> 2, wn = w & 3;
    const int bm = blockIdx.y * 128, bn = blockIdx.x * 128;

    uint32_t adst[2], bdst[2];
    const __half* gA[2];
    const __half* gB1[2];
    const __half* gB2[2];
    int bsz[2];
#pragma unroll
    for (int p = 0; p < 2; p++) {
        int c = t + p * 256;
        int m = c >> 2, cb = (c & 3) * 16, koff = (c & 3) * 8;
        adst[p] = (uint32_t)(m * STG_PITCH + cb);
        bdst[p] = (uint32_t)(STG_A + m * STG_PITCH + cb);
        gA[p] = A + (size_t)(bm + m) * lda + koff;
        int gn = bn + m;
        bool val = (gn < nvalid);
        gB1[p] = B1 + (size_t)(val ? gn : 0) * ldb + koff;
        gB2[p] = B2 + (size_t)(val ? gn : 0) * ldb + koff;
        bsz[p] = val ? 16 : 0;
    }
    const int q = ln >> 3, lr = ln & 7;
    const uint32_t aBase = sb + (uint32_t)((wm * 64 + (q & 1) * 8 + lr) * STG_PITCH + (q >> 1) * 16);
    const uint32_t bBase = sb + (uint32_t)(STG_A + (wn * 32 + (q >> 1) * 8 + lr) * STG_PITCH + (q & 1) * 16);

    const int nCh = K >> 5;
    auto issue = [&](int i) {
        if (i < nCh) {
            uint32_t base = sb + (uint32_t)(i % FF_NSTAGE) * FF_STG_SZ;
#pragma unroll
            for (int p = 0; p < 2; p++) {
                cpa16(base + adst[p],          gA[p]  + i * 32, 16);
                cpa16(base + bdst[p],          gB1[p] + i * 32, bsz[p]);
                cpa16(base + bdst[p] + STG_A,  gB2[p] + i * 32, bsz[p]);
            }
        }
        CP_COMMIT();
    };

    float ac1[4][4][4], ac2[4][4][4];
#pragma unroll
    for (int i = 0; i < 4; i++)
#pragma unroll
        for (int j = 0; j < 4; j++)
#pragma unroll
            for (int r = 0; r < 4; r++) { ac1[i][j][r] = 0.f; ac2[i][j][r] = 0.f; }

    issue(0); issue(1); issue(2); issue(3);
    for (int i = 0; i < nCh; i++) {
        asm volatile("cp.async.wait_group %0;" :: "n"(FF_NSTAGE - 2) : "memory");
        __syncthreads();
        issue(i + FF_NSTAGE - 1);
        uint32_t so = (uint32_t)(i % FF_NSTAGE) * FF_STG_SZ;
#pragma unroll
        for (int ks = 0; ks < 2; ks++) {
            uint32_t af[4][4], b1[4][2], b2[4][2];
#pragma unroll
            for (int mf = 0; mf < 4; mf++)
                ldsm4(af[mf], aBase + so + mf * (16 * STG_PITCH) + ks * 32);
#pragma unroll
            for (int nfp = 0; nfp < 2; nfp++) {
                uint32_t rr[4];
                ldsm4(rr, bBase + so + nfp * (16 * STG_PITCH) + ks * 32);
                b1[nfp * 2 + 0][0] = rr[0]; b1[nfp * 2 + 0][1] = rr[1];
                b1[nfp * 2 + 1][0] = rr[2]; b1[nfp * 2 + 1][1] = rr[3];
                ldsm4(rr, bBase + so + STG_A + nfp * (16 * STG_PITCH) + ks * 32);
                b2[nfp * 2 + 0][0] = rr[0]; b2[nfp * 2 + 0][1] = rr[1];
                b2[nfp * 2 + 1][0] = rr[2]; b2[nfp * 2 + 1][1] = rr[3];
            }
#pragma unroll
            for (int ii = 0; ii < 4; ii++)
#pragma unroll
                for (int j = 0; j < 4; j++) {
                    mma_f16(ac1[ii][j], af[ii], b1[j]);
                    mma_f16(ac2[ii][j], af[ii], b2[j]);
                }
        }
    }

    const int g4 = ln >> 2, t4 = ln & 3;
#pragma unroll
    for (int ii = 0; ii < 4; ii++) {
        int row0 = bm + wm * 64 + ii * 16 + g4;
#pragma unroll
        for (int j = 0; j < 4; j++) {
            int col = bn + wn * 32 + j * 8 + t4 * 2;
            if (col < nvalid) {
#pragma unroll
                for (int h = 0; h < 2; h++) {
                    int r = row0 + h * 8;
                    size_t idx = (size_t)r * ldc + col;
                    float a0 = ac1[ii][j][h * 2 + 0], a1 = ac1[ii][j][h * 2 + 1];
                    float b0 = ac2[ii][j][h * 2 + 0], b1v = ac2[ii][j][h * 2 + 1];
                    float v0 = a0 * sigf(a0) * b0;
                    float v1 = a1 * sigf(a1) * b1v;
                    *reinterpret_cast<__half2*>(C + idx) = __floats2half2_rn(v0, v1);
                }
            }
        }
    }
}

// ---------------- fused scan + big weight prep (R13 config: CHK=128) ----------------
#define CHK   128
#define WNUP  160
#define SCAN_BLOCKS 64
#define PREP_BLOCKS 448

__global__ void scanprep_kernel(const float* __restrict__ gates,
                                const float* __restrict__ Bx,
                                __half* __restrict__ hs,
                                const float* __restrict__ w1,
                                const float* __restrict__ w2,
                                const float* __restrict__ w3) {
    __shared__ float hp[2][16 * 17];
    if (blockIdx.x >= SCAN_BLOCKS) {
        size_t pb = blockIdx.x - SCAN_BLOCKS;
        size_t stride = (size_t)(gridDim.x - SCAN_BLOCKS) * 256;
        size_t tid0 = pb * 256 + threadIdx.x;
        for (size_t i = tid0; i < (size_t)P3; i += stride) {
            size_t off = i * 2;
            const float* src; __half* dst;
            if (off < (size_t)P3) { src = w1; dst = g_w1h; }
            else { off -= (size_t)P3; src = w2; dst = g_w2h; }
            float2 v = *reinterpret_cast<const float2*>(src + off);
            *reinterpret_cast<__half2*>(dst + off) = __floats2half2_rn(v.x, v.y);
        }
        size_t pairs3 = (size_t)DD * DFFP / 2;
        for (size_t i = tid0; i < pairs3; i += stride) {
            size_t j2 = i * 2;
            int d = (int)(j2 / DFFP);
            int j = (int)(j2 % DFFP);
            __half2 o;
            if (j < DFF) {
                float2 v = *reinterpret_cast<const float2*>(w3 + (size_t)d * DFF + j);
                o = __floats2half2_rn(v.x, v.y);
            } else {
                o = __floats2half2_rn(0.f, 0.f);
            }
            *reinterpret_cast<__half2*>(g_w3h + (size_t)d * DFFP + j) = o;
        }
        return;
    }
    int chunk = blockIdx.x & 15, bat = blockIdx.x >> 4;
    int s0 = chunk * CHK, send = s0 + CHK;
    int sw = (chunk == 0) ? 0 : s0 - WNUP;
    int t = threadIdx.x;
    int c = t >> 4, i = t & 15;

    float Rrow[16], Lrow[16];
#pragma unroll
    for (int j = 0; j < 16; j++) {
        Rrow[j] = g_RQ[(c * 16 + i) * 16 + j];
        Lrow[j] = g_LQ[(i * 16 + c) * 16 + j];
    }
    float val = 0.f;

    size_t base = (size_t)bat * SS;
    float bx_n = Bx[(base + sw) * NN + t];
    float al_n = gates[(base + sw) * 32 + i];
    float be_n = gates[(base + sw) * 32 + 16 + c];

    for (int s = sw; s < send; s++) {
        float bx = bx_n, al = al_n, be = be_n;
        if (s + 1 < send) {
            size_t rn = base + s + 1;
            bx_n = Bx[rn * NN + t];
            al_n = gates[rn * 32 + i];
            be_n = gates[rn * 32 + 16 + c];
        }
        float acc0 = 0.f, acc1 = 0.f;
#pragma unroll
        for (int j = 0; j < 16; j += 2) {
            float h0 = __shfl_sync(0xffffffffu, val, j, 16);
            float h1 = __shfl_sync(0xffffffffu, val, j + 1, 16);
            acc0 = fmaf(Rrow[j], h0, acc0);
            acc1 = fmaf(Rrow[j + 1], h1, acc1);
        }
        float* hpb = hp[s & 1];
        hpb[i * 17 + c] = be * (acc0 + acc1);
        __syncthreads();
        float acc2 = 0.f, acc3 = 0.f;
#pragma unroll
        for (int j = 0; j < 16; j += 2) {
            acc2 = fmaf(Lrow[j],     hpb[i * 17 + j],     acc2);
            acc3 = fmaf(Lrow[j + 1], hpb[i * 17 + j + 1], acc3);
        }
        val = al * (acc2 + acc3) + bx;
        if (s >= s0) hs[(base + s) * NN + t] = __float2half(val);
    }
}

// ---------------- launcher ----------------
#define GEMM_SMEM (NSTAGE * STG_SZ)
#define FF_SMEM   (FF_NSTAGE * FF_STG_SZ)

extern "C" void kernel_launch(void* const* d_in, const int* in_sizes, int n_in,
                              void* d_out, int out_size) {
    const float* x     = (const float*)d_in[0];
    const float* Lskew = (const float*)d_in[1];
    const float* Rskew = (const float*)d_in[2];
    const float* Wg    = (const float*)d_in[3];
    const float* bg    = (const float*)d_in[4];
    const float* WB    = (const float*)d_in[5];
    const float* bB    = (const float*)d_in[6];
    const float* WC    = (const float*)d_in[7];
    const float* bC    = (const float*)d_in[8];
    const float* n1w   = (const float*)d_in[9];
    const float* n2w   = (const float*)d_in[10];
    const float* w1    = (const float*)d_in[11];
    const float* w2    = (const float*)d_in[12];
    const float* w3    = (const float*)d_in[13];
    float* out = (float*)d_out;

    __half *xsh, *hsh, *s1h, *wcb, *wch, *w1h, *w2h, *w3h;
    float *gatesb, *bxb;
    cudaGetSymbolAddress((void**)&xsh,    g_xsh);
    cudaGetSymbolAddress((void**)&gatesb, g_gates);
    cudaGetSymbolAddress((void**)&bxb,    g_bx);
    cudaGetSymbolAddress((void**)&hsh,    g_hsh);
    cudaGetSymbolAddress((void**)&s1h,    g_s1h);
    cudaGetSymbolAddress((void**)&wcb,    g_wcb);
    cudaGetSymbolAddress((void**)&wch,    g_wch);
    cudaGetSymbolAddress((void**)&w1h,    g_w1h);
    cudaGetSymbolAddress((void**)&w2h,    g_w2h);
    cudaGetSymbolAddress((void**)&w3h,    g_w3h);

    cudaFuncSetAttribute(mma_h_kernel<EPI_BXG>,     cudaFuncAttributeMaxDynamicSharedMemorySize, GEMM_SMEM);
    cudaFuncSetAttribute(mma_h_kernel<EPI_BIASRES>, cudaFuncAttributeMaxDynamicSharedMemorySize, GEMM_SMEM);
    cudaFuncSetAttribute(mma_h_kernel<EPI_RES>,     cudaFuncAttributeMaxDynamicSharedMemorySize, GEMM_SMEM);
    cudaFuncSetAttribute(ff_fused_kernel,           cudaFuncAttributeMaxDynamicSharedMemorySize, FF_SMEM);

    // 1. fused init: cayley + small prep + rmsnorm1  (3 launches -> 1)
    init_kernel<<<INIT_BLOCKS, 256>>>(x, n1w, Lskew, Rskew, Wg, WB, WC, xsh);
    // 2. combined: Bx = xs@WB^T + bB, gates = sigmoid(xs@Wg^T + bg)
    {
        dim3 g((NCOMB + 127) / 128, ROWS / 128);
        mma_h_kernel<EPI_BXG><<<g, 256, GEMM_SMEM>>>(xsh, DD, wcb, DD, NCOMB, bxb, NN, bB, bg, DD);
    }
    // 3. fused: windowed scan (blocks 0-63, CHK=128) + big weight prep (blocks 64+)
    scanprep_kernel<<<SCAN_BLOCKS + PREP_BLOCKS, 256>>>(gatesb, bxb, hsh, w1, w2, w3);
    // 4. out = x + hs @ WC^T + bC
    {
        dim3 g(DD / 128, ROWS / 128);
        mma_h_kernel<EPI_BIASRES><<<g, 256, GEMM_SMEM>>>(hsh, NN, wch, NN, DD, out, DD, bC, x, NN);
    }
    // 5. xs = half(rmsnorm(out, norm2_w))
    rmsnorm_h_kernel<<<ROWS, 256>>>(out, n2w, xsh);
    // 6. s1h = half(silu(xs@w1^T) * (xs@w2^T))   (fused FF, 5-stage)
    {
        dim3 g((DFF + 127) / 128, ROWS / 128);
        ff_fused_kernel<<<g, 256, FF_SMEM>>>(xsh, DD, w1h, w2h, DD, DFF, s1h, DFFP, DD);
    }
    // 7. out += s1h @ w3h^T
    {
        dim3 g(DD / 128, ROWS / 128);
        mma_h_kernel<EPI_RES><<<g, 256, GEMM_SMEM>>>(s1h, DFFP, w3h, DFFP, DD, out, DD, nullptr, out, DFFP);
    }
}